// round 16
// baseline (speedup 1.0000x reference)
#include <cuda_runtime.h>
#include <cuda_bf16.h>
#include <cstddef>
#include <cstdint>

// Problem constants
#define BB 512
#define TT 256
#define DD 128
#define HH 128
#define SS 32
#define BT (BB*TT)   // 131072

typedef unsigned long long u64;
typedef uint32_t u32;

// ---------------------------------------------------------------------------
// Device-global scratch
// ---------------------------------------------------------------------------
__device__ float g_Xz[(size_t)BT * HH];
__device__ float g_Xr[(size_t)BT * HH];
__device__ float g_Xh[(size_t)BT * HH];
__device__ float g_gh[(size_t)BT * HH];
// bf16 hi/lo copies, layout [j][d]:
// 0=W_z 1=V_z 2=W_r 3=V_r 4=W_h 5=V_h 6=W_dg_h 7=U_z 8=U_r 9=U_h
__device__ __nv_bfloat16 g_Wbh[10 * 16384];
__device__ __nv_bfloat16 g_Wbl[10 * 16384];

__global__ void noop_kernel() {}

// ---------------------------------------------------------------------------
// Kernel 0: convert 10 weight matrices fp32 -> bf16 hi/lo
// ---------------------------------------------------------------------------
__global__ void convert_w(const float* __restrict__ Wz, const float* __restrict__ Vz,
                          const float* __restrict__ Wr, const float* __restrict__ Vr,
                          const float* __restrict__ Wh, const float* __restrict__ Vh,
                          const float* __restrict__ Wdgh,
                          const float* __restrict__ Uz, const float* __restrict__ Ur,
                          const float* __restrict__ Uh)
{
    const float* srcs[10] = {Wz, Vz, Wr, Vr, Wh, Vh, Wdgh, Uz, Ur, Uh};
    const float* s = srcs[blockIdx.x];
    __nv_bfloat16* dh = g_Wbh + blockIdx.x * 16384;
    __nv_bfloat16* dl = g_Wbl + blockIdx.x * 16384;
    for (int idx = threadIdx.x; idx < 16384; idx += blockDim.x) {
        float v = s[idx];
        __nv_bfloat16 h = __float2bfloat16(v);
        dh[idx] = h;
        dl[idx] = __float2bfloat16(v - __bfloat162float(h));
    }
}

// ---------------------------------------------------------------------------
// Shared HMMA helpers
// ---------------------------------------------------------------------------
#define PA 136

__device__ __forceinline__ void mma_bf16(float c[4], u32 a0, u32 a1, u32 a2, u32 a3,
                                         u32 b0, u32 b1) {
    asm("mma.sync.aligned.m16n8k16.row.col.f32.bf16.bf16.f32 "
        "{%0,%1,%2,%3}, {%4,%5,%6,%7}, {%8,%9}, {%0,%1,%2,%3};"
        : "+f"(c[0]), "+f"(c[1]), "+f"(c[2]), "+f"(c[3])
        : "r"(a0), "r"(a1), "r"(a2), "r"(a3), "r"(b0), "r"(b1));
}
__device__ __forceinline__ void ldsm4(u32& r0, u32& r1, u32& r2, u32& r3, u32 a) {
    asm volatile("ldmatrix.sync.aligned.m8n8.x4.shared.b16 {%0,%1,%2,%3}, [%4];"
                 : "=r"(r0), "=r"(r1), "=r"(r2), "=r"(r3) : "r"(a));
}

// ---------------------------------------------------------------------------
// Kernel 1: precompute via warp-level mma.sync (unchanged from R13, 377us)
// ---------------------------------------------------------------------------
#define PANEL_B (128 * PA * 2)
#define SM_BIAS  0
#define SM_AHI   512
#define SM_ALO   (SM_AHI + PANEL_B)
#define SM_MBF   (SM_ALO + PANEL_B)
#define SM_WHI   (SM_MBF + PANEL_B)
#define SM_WLO   (SM_WHI + PANEL_B)
#define SM_TOTAL (SM_WLO + PANEL_B)

__device__ __forceinline__ void gpass(const __nv_bfloat16* __restrict__ A,
                                      const __nv_bfloat16* __restrict__ W,
                                      float acc[2][8][4], int row0, int col0, int lane)
{
    const int ar = lane & 15, ac = (lane >> 4) << 3;
    const int bj = ((lane >> 4) << 3) + (lane & 7);
    const int bk = ((lane >> 3) & 1) << 3;
    #pragma unroll
    for (int kt = 0; kt < 8; kt++) {
        const int k0 = kt * 16;
        u32 a[2][4];
        #pragma unroll
        for (int mt = 0; mt < 2; mt++) {
            u32 ad = (u32)__cvta_generic_to_shared(A + (row0 + mt * 16 + ar) * PA + k0 + ac);
            ldsm4(a[mt][0], a[mt][1], a[mt][2], a[mt][3], ad);
        }
        u32 b[4][4];
        #pragma unroll
        for (int np = 0; np < 4; np++) {
            u32 bd = (u32)__cvta_generic_to_shared(W + (col0 + np * 16 + bj) * PA + k0 + bk);
            ldsm4(b[np][0], b[np][1], b[np][2], b[np][3], bd);
        }
        #pragma unroll
        for (int mt = 0; mt < 2; mt++)
            #pragma unroll
            for (int nt = 0; nt < 8; nt++)
                mma_bf16(acc[mt][nt], a[mt][0], a[mt][1], a[mt][2], a[mt][3],
                         b[nt >> 1][(nt & 1) * 2], b[nt >> 1][(nt & 1) * 2 + 1]);
    }
}

__device__ __forceinline__ void gpassAA(const __nv_bfloat16* __restrict__ A0,
                                        const __nv_bfloat16* __restrict__ A1,
                                        const __nv_bfloat16* __restrict__ W,
                                        float acc[2][8][4], int row0, int col0, int lane)
{
    const int ar = lane & 15, ac = (lane >> 4) << 3;
    const int bj = ((lane >> 4) << 3) + (lane & 7);
    const int bk = ((lane >> 3) & 1) << 3;
    #pragma unroll
    for (int kt = 0; kt < 8; kt++) {
        const int k0 = kt * 16;
        u32 a0[2][4], a1[2][4];
        #pragma unroll
        for (int mt = 0; mt < 2; mt++) {
            u32 ad0 = (u32)__cvta_generic_to_shared(A0 + (row0 + mt * 16 + ar) * PA + k0 + ac);
            ldsm4(a0[mt][0], a0[mt][1], a0[mt][2], a0[mt][3], ad0);
            u32 ad1 = (u32)__cvta_generic_to_shared(A1 + (row0 + mt * 16 + ar) * PA + k0 + ac);
            ldsm4(a1[mt][0], a1[mt][1], a1[mt][2], a1[mt][3], ad1);
        }
        u32 b[4][4];
        #pragma unroll
        for (int np = 0; np < 4; np++) {
            u32 bd = (u32)__cvta_generic_to_shared(W + (col0 + np * 16 + bj) * PA + k0 + bk);
            ldsm4(b[np][0], b[np][1], b[np][2], b[np][3], bd);
        }
        #pragma unroll
        for (int mt = 0; mt < 2; mt++)
            #pragma unroll
            for (int nt = 0; nt < 8; nt++) {
                mma_bf16(acc[mt][nt], a0[mt][0], a0[mt][1], a0[mt][2], a0[mt][3],
                         b[nt >> 1][(nt & 1) * 2], b[nt >> 1][(nt & 1) * 2 + 1]);
                mma_bf16(acc[mt][nt], a1[mt][0], a1[mt][1], a1[mt][2], a1[mt][3],
                         b[nt >> 1][(nt & 1) * 2], b[nt >> 1][(nt & 1) * 2 + 1]);
            }
    }
}

__device__ __forceinline__ void gpassBB(const __nv_bfloat16* __restrict__ A,
                                        const __nv_bfloat16* __restrict__ W0,
                                        const __nv_bfloat16* __restrict__ W1,
                                        float acc[2][8][4], int row0, int col0, int lane)
{
    const int ar = lane & 15, ac = (lane >> 4) << 3;
    const int bj = ((lane >> 4) << 3) + (lane & 7);
    const int bk = ((lane >> 3) & 1) << 3;
    #pragma unroll
    for (int kt = 0; kt < 8; kt++) {
        const int k0 = kt * 16;
        u32 a[2][4];
        #pragma unroll
        for (int mt = 0; mt < 2; mt++) {
            u32 ad = (u32)__cvta_generic_to_shared(A + (row0 + mt * 16 + ar) * PA + k0 + ac);
            ldsm4(a[mt][0], a[mt][1], a[mt][2], a[mt][3], ad);
        }
        u32 b0[4][4], b1[4][4];
        #pragma unroll
        for (int np = 0; np < 4; np++) {
            u32 bd0 = (u32)__cvta_generic_to_shared(W0 + (col0 + np * 16 + bj) * PA + k0 + bk);
            ldsm4(b0[np][0], b0[np][1], b0[np][2], b0[np][3], bd0);
            u32 bd1 = (u32)__cvta_generic_to_shared(W1 + (col0 + np * 16 + bj) * PA + k0 + bk);
            ldsm4(b1[np][0], b1[np][1], b1[np][2], b1[np][3], bd1);
        }
        #pragma unroll
        for (int mt = 0; mt < 2; mt++)
            #pragma unroll
            for (int nt = 0; nt < 8; nt++) {
                mma_bf16(acc[mt][nt], a[mt][0], a[mt][1], a[mt][2], a[mt][3],
                         b0[nt >> 1][(nt & 1) * 2], b0[nt >> 1][(nt & 1) * 2 + 1]);
                mma_bf16(acc[mt][nt], a[mt][0], a[mt][1], a[mt][2], a[mt][3],
                         b1[nt >> 1][(nt & 1) * 2], b1[nt >> 1][(nt & 1) * 2 + 1]);
            }
    }
}

__device__ __forceinline__ void stage_w(char* smem, int off, const __nv_bfloat16* g) {
    const uint4* src = (const uint4*)g;
    #pragma unroll
    for (int it = 0; it < 8; it++) {
        int cc = threadIdx.x + it * 256;
        int j = cc >> 4, k8 = (cc & 15) * 8;
        *(uint4*)(smem + off + (j * PA + k8) * 2) = src[cc];
    }
}

__global__ __launch_bounds__(256, 1)
void precompute_mma(const float* __restrict__ x,     const float* __restrict__ mask,
                    const float* __restrict__ delta, const float* __restrict__ xlast,
                    const float* __restrict__ x_mean,
                    const float* __restrict__ w_dg_x, const float* __restrict__ b_dg_x,
                    const float* __restrict__ b_dg_h,
                    const float* __restrict__ b_z, const float* __restrict__ b_r,
                    const float* __restrict__ b_h)
{
    extern __shared__ char smem[];
    float* bias_s = (float*)(smem + SM_BIAS);
    __nv_bfloat16* Ahi = (__nv_bfloat16*)(smem + SM_AHI);
    __nv_bfloat16* Alo = (__nv_bfloat16*)(smem + SM_ALO);
    __nv_bfloat16* Mbf = (__nv_bfloat16*)(smem + SM_MBF);
    __nv_bfloat16* Whi = (__nv_bfloat16*)(smem + SM_WHI);
    __nv_bfloat16* Wlo = (__nv_bfloat16*)(smem + SM_WLO);

    const int tid  = threadIdx.x;
    const int lane = tid & 31;
    const int wrp  = tid >> 5;
    const int row0 = (wrp & 3) * 32;
    const int col0 = (wrp >> 2) * 64;
    const int brow = blockIdx.x * 128;
    const int b    = brow >> 8;
    const int g = lane >> 2, t = lane & 3;

    float acc[2][8][4];

    for (int idx = tid; idx < 128 * 128; idx += 256) {
        int r = idx >> 7, d = idx & 127;
        float v = delta[(size_t)(brow + r) * DD + d];
        __nv_bfloat16 hi = __float2bfloat16(v);
        Ahi[r * PA + d] = hi;
        Alo[r * PA + d] = __float2bfloat16(v - __bfloat162float(hi));
    }
    stage_w(smem, SM_WHI, g_Wbh + 6 * 16384);
    stage_w(smem, SM_WLO, g_Wbl + 6 * 16384);
    if (tid < 128) bias_s[tid] = b_dg_h[tid];
    __syncthreads();

    #pragma unroll
    for (int mt = 0; mt < 2; mt++)
        #pragma unroll
        for (int nt = 0; nt < 8; nt++)
            #pragma unroll
            for (int q = 0; q < 4; q++) acc[mt][nt][q] = 0.0f;
    gpassAA(Ahi, Alo, Whi, acc, row0, col0, lane);
    gpass(Ahi, Wlo, acc, row0, col0, lane);
    #pragma unroll
    for (int mt = 0; mt < 2; mt++)
        #pragma unroll
        for (int nt = 0; nt < 8; nt++) {
            int j0 = col0 + nt * 8 + 2 * t;
            float2 bv = *(const float2*)&bias_s[j0];
            size_t r0g = (size_t)(brow + row0 + mt * 16 + g) * HH + j0;
            size_t r8g = r0g + (size_t)8 * HH;
            *(float2*)&g_gh[r0g] = make_float2(__expf(-fmaxf(acc[mt][nt][0] + bv.x, 0.0f)),
                                               __expf(-fmaxf(acc[mt][nt][1] + bv.y, 0.0f)));
            *(float2*)&g_gh[r8g] = make_float2(__expf(-fmaxf(acc[mt][nt][2] + bv.x, 0.0f)),
                                               __expf(-fmaxf(acc[mt][nt][3] + bv.y, 0.0f)));
        }
    __syncthreads();

    for (int idx = tid; idx < 128 * 128; idx += 256) {
        int r = idx >> 7, d = idx & 127;
        size_t gg = (size_t)(brow + r) * DD + d;
        float xv = x[gg], mv = mask[gg], dl = delta[gg], xl = xlast[gg];
        float gx = __expf(-fmaxf(fmaf(w_dg_x[d], dl, b_dg_x[d]), 0.0f));
        float xm = x_mean[b * DD + d];
        float xh = mv * xv + (1.0f - mv) * (gx * xl + (1.0f - gx) * xm);
        __nv_bfloat16 hi = __float2bfloat16(xh);
        Ahi[r * PA + d] = hi;
        Alo[r * PA + d] = __float2bfloat16(xh - __bfloat162float(hi));
        Mbf[r * PA + d] = __float2bfloat16(mv);
    }
    __syncthreads();

    const int wi[3] = {0, 2, 4};
    const int vi[3] = {1, 3, 5};
    const float* biases[3] = {b_z, b_r, b_h};
    float* outs[3] = {g_Xz, g_Xr, g_Xh};

    #pragma unroll 1
    for (int gate = 0; gate < 3; gate++) {
        stage_w(smem, SM_WHI, g_Wbh + wi[gate] * 16384);
        stage_w(smem, SM_WLO, g_Wbl + wi[gate] * 16384);
        if (tid < 128) bias_s[tid] = biases[gate][tid];
        __syncthreads();

        #pragma unroll
        for (int mt = 0; mt < 2; mt++)
            #pragma unroll
            for (int nt = 0; nt < 8; nt++)
                #pragma unroll
                for (int q = 0; q < 4; q++) acc[mt][nt][q] = 0.0f;

        gpassAA(Ahi, Alo, Whi, acc, row0, col0, lane);
        gpass(Ahi, Wlo, acc, row0, col0, lane);

        __syncthreads();
        stage_w(smem, SM_WHI, g_Wbh + vi[gate] * 16384);
        stage_w(smem, SM_WLO, g_Wbl + vi[gate] * 16384);
        __syncthreads();
        gpassBB(Mbf, Whi, Wlo, acc, row0, col0, lane);

        float* obase = outs[gate];
        #pragma unroll
        for (int mt = 0; mt < 2; mt++)
            #pragma unroll
            for (int nt = 0; nt < 8; nt++) {
                int j0 = col0 + nt * 8 + 2 * t;
                float2 bv = *(const float2*)&bias_s[j0];
                size_t r0g = (size_t)(brow + row0 + mt * 16 + g) * HH + j0;
                size_t r8g = r0g + (size_t)8 * HH;
                *(float2*)&obase[r0g] = make_float2(acc[mt][nt][0] + bv.x, acc[mt][nt][1] + bv.y);
                *(float2*)&obase[r8g] = make_float2(acc[mt][nt][2] + bv.x, acc[mt][nt][3] + bv.y);
            }
        __syncthreads();
    }
}

// ---------------------------------------------------------------------------
// Kernel 2: HMMA recurrence. 32 CTAs x 16 batch rows x 256 threads.
// U panels (6x bf16 hi/lo, [j][k] pitch 136) resident in smem all 256 steps.
// h state fp32 in smem (pitch 17). Per step: owner threads build h*gamma
// bf16 panels; warps 0-3 z-GEMM, 4-7 r-GEMM; r-warps publish r*h panels;
// warps 0-3 h_tilde-GEMM (zg kept in regs at same lanes) + h update.
// ---------------------------------------------------------------------------
#define RU(i)   ((i) * 34816)               // 6 U panels
#define R_PHI   208896                       // h' / rh hi panel (16 x PA bf16)
#define R_PLO   (R_PHI + 4352)
#define R_HS    (R_PLO + 4352)               // fp32 [j*17 + row], 128*17*4
#define R_TOTAL (R_HS + 128 * 17 * 4)        // 226304 bytes

// one 16x128x128 matvec pass (single m-tile), 4 n-tiles at col0
__device__ __forceinline__ void mvpass(const char* smem, int aoff, int boff,
                                       float acc[4][4], int col0, int lane)
{
    const int ar = lane & 15, ac = (lane >> 4) << 3;
    const int bj = ((lane >> 4) << 3) + (lane & 7);
    const int bk = ((lane >> 3) & 1) << 3;
    #pragma unroll
    for (int kt = 0; kt < 8; kt++) {
        const int k0 = kt * 16;
        u32 a[4];
        u32 ad = (u32)__cvta_generic_to_shared(smem + aoff + (ar * PA + k0 + ac) * 2);
        ldsm4(a[0], a[1], a[2], a[3], ad);
        u32 b[2][4];
        #pragma unroll
        for (int np = 0; np < 2; np++) {
            u32 bd = (u32)__cvta_generic_to_shared(
                smem + boff + ((col0 + np * 16 + bj) * PA + k0 + bk) * 2);
            ldsm4(b[np][0], b[np][1], b[np][2], b[np][3], bd);
        }
        #pragma unroll
        for (int nt = 0; nt < 4; nt++)
            mma_bf16(acc[nt], a[0], a[1], a[2], a[3],
                     b[nt >> 1][(nt & 1) * 2], b[nt >> 1][(nt & 1) * 2 + 1]);
    }
}

// load 16 gate inputs at D-fragment lanes for time t
__device__ __forceinline__ void ldgate(float xg[16], const float* base,
                                       int b0, int t, int col0, int g, int tl)
{
    #pragma unroll
    for (int nt = 0; nt < 4; nt++) {
        int j0 = col0 + nt * 8 + 2 * tl;
        size_t a0 = ((size_t)(b0 + g) * TT + t) * HH + j0;
        size_t a8 = ((size_t)(b0 + g + 8) * TT + t) * HH + j0;
        float2 v0 = *(const float2*)&base[a0];
        float2 v8 = *(const float2*)&base[a8];
        xg[nt * 4 + 0] = v0.x; xg[nt * 4 + 1] = v0.y;
        xg[nt * 4 + 2] = v8.x; xg[nt * 4 + 3] = v8.y;
    }
}

__global__ __launch_bounds__(256, 1)
void recurrent_mma(const float* __restrict__ hs0,
                   const float* __restrict__ statics,
                   const float* __restrict__ W_out, const float* __restrict__ b_out,
                   float* __restrict__ out)
{
    extern __shared__ char smem[];
    __nv_bfloat16* PHI = (__nv_bfloat16*)(smem + R_PHI);
    __nv_bfloat16* PLO = (__nv_bfloat16*)(smem + R_PLO);
    float* hS = (float*)(smem + R_HS);     // [j*17 + row]

    const int tid  = threadIdx.x;
    const int lane = tid & 31;
    const int wrp  = tid >> 5;
    const int g    = lane >> 2, tl = lane & 3;
    const bool isZ = wrp < 4;
    const int col0 = (wrp & 3) * 32;
    const int b0   = blockIdx.x * 16;

    // stage 6 U panels: z(7), r(8), h(9) hi/lo
    stage_w(smem, RU(0), g_Wbh + 7 * 16384);
    stage_w(smem, RU(1), g_Wbl + 7 * 16384);
    stage_w(smem, RU(2), g_Wbh + 8 * 16384);
    stage_w(smem, RU(3), g_Wbl + 8 * 16384);
    stage_w(smem, RU(4), g_Wbh + 9 * 16384);
    stage_w(smem, RU(5), g_Wbl + 9 * 16384);

    // init h state: hS[j*17+row] = hs0[(b0+row)*HH + j]
    for (int idx = tid; idx < 16 * 128; idx += 256) {
        int row = idx >> 7, j = idx & 127;
        hS[j * 17 + row] = hs0[(b0 + row) * HH + j];
    }

    // owner mapping for S1: col = tid>>1, rows p*8..p*8+7
    const int ocol = tid >> 1;
    const int op   = tid & 1;

    // prefetch t=0 operands
    float gm[8];
    #pragma unroll
    for (int i = 0; i < 8; i++)
        gm[i] = g_gh[((size_t)(b0 + op * 8 + i) * TT + 0) * HH + ocol];
    float xzr[16], xh[16];
    ldgate(xzr, isZ ? g_Xz : g_Xr, b0, 0, col0, g, tl);
    if (isZ) ldgate(xh, g_Xh, b0, 0, col0, g, tl);
    __syncthreads();

    float zg[4][4];

    #pragma unroll 1
    for (int t = 0; t < TT; t++) {
        // ---- S1: h' = gamma*h; update hS in place; build bf16 panels ----
        #pragma unroll
        for (int i = 0; i < 8; i++) {
            int row = op * 8 + i;
            float h = hS[ocol * 17 + row];
            float hp = gm[i] * h;
            hS[ocol * 17 + row] = hp;
            __nv_bfloat16 hi = __float2bfloat16(hp);
            PHI[row * PA + ocol] = hi;
            PLO[row * PA + ocol] = __float2bfloat16(hp - __bfloat162float(hi));
            if (t + 1 < TT)
                gm[i] = g_gh[((size_t)(b0 + row) * TT + t + 1) * HH + ocol];
        }
        __syncthreads();   // B1: panels + hS' ready

        // ---- z / r GEMM (all warps) ----
        float acc[4][4];
        #pragma unroll
        for (int nt = 0; nt < 4; nt++)
            #pragma unroll
            for (int c = 0; c < 4; c++) acc[nt][c] = 0.0f;
        const int uh = isZ ? RU(0) : RU(2);
        const int ul = isZ ? RU(1) : RU(3);
        mvpass(smem, R_PHI, uh, acc, col0, lane);
        mvpass(smem, R_PLO, uh, acc, col0, lane);
        mvpass(smem, R_PHI, ul, acc, col0, lane);
        __syncthreads();   // B2: all ldsm of h panels done (safe to overwrite)

        if (isZ) {
            #pragma unroll
            for (int nt = 0; nt < 4; nt++)
                #pragma unroll
                for (int c = 0; c < 4; c++)
                    zg[nt][c] = 1.0f / (1.0f + __expf(-(acc[nt][c] + xzr[nt * 4 + c])));
            if (t + 1 < TT) ldgate(xzr, g_Xz, b0, t + 1, col0, g, tl);
        } else {
            // r gate -> publish r*h (bf16 hi/lo) into panels
            #pragma unroll
            for (int nt = 0; nt < 4; nt++) {
                int j0 = col0 + nt * 8 + 2 * tl;
                #pragma unroll
                for (int c = 0; c < 4; c++) {
                    int row = g + ((c >> 1) << 3);
                    int j   = j0 + (c & 1);
                    float rg = 1.0f / (1.0f + __expf(-(acc[nt][c] + xzr[nt * 4 + c])));
                    float rh = rg * hS[j * 17 + row];
                    __nv_bfloat16 hi = __float2bfloat16(rh);
                    PHI[row * PA + j] = hi;
                    PLO[row * PA + j] = __float2bfloat16(rh - __bfloat162float(hi));
                }
            }
            if (t + 1 < TT) ldgate(xzr, g_Xr, b0, t + 1, col0, g, tl);
        }
        __syncthreads();   // B3: rh panels ready

        // ---- h_tilde GEMM + h update (warps 0-3 only) ----
        if (isZ) {
            float ac2[4][4];
            #pragma unroll
            for (int nt = 0; nt < 4; nt++)
                #pragma unroll
                for (int c = 0; c < 4; c++) ac2[nt][c] = 0.0f;
            mvpass(smem, R_PHI, RU(4), ac2, col0, lane);
            mvpass(smem, R_PLO, RU(4), ac2, col0, lane);
            mvpass(smem, R_PHI, RU(5), ac2, col0, lane);
            #pragma unroll
            for (int nt = 0; nt < 4; nt++) {
                int j0 = col0 + nt * 8 + 2 * tl;
                #pragma unroll
                for (int c = 0; c < 4; c++) {
                    int row = g + ((c >> 1) << 3);
                    int j   = j0 + (c & 1);
                    float pre = ac2[nt][c] + xh[nt * 4 + c];
                    float ht = 2.0f / (1.0f + __expf(-2.0f * pre)) - 1.0f;
                    float hp = hS[j * 17 + row];
                    float z = zg[nt][c];
                    hS[j * 17 + row] = (1.0f - z) * hp + z * ht;
                }
            }
            if (t + 1 < TT) ldgate(xh, g_Xh, b0, t + 1, col0, g, tl);
        }
        __syncthreads();   // B4: hS updated
    }

    // ---- classifier: 16 rows, threads 0-15 ----
    if (tid < 16) {
        float acc = 0.0f;
        #pragma unroll 4
        for (int j = 0; j < HH; j++)
            acc = fmaf(hS[j * 17 + tid], W_out[j], acc);
        float sacc = 0.0f;
        #pragma unroll
        for (int s = 0; s < SS; s++)
            sacc = fmaf(statics[(b0 + tid) * SS + s], W_out[HH + s], sacc);
        out[b0 + tid] = acc + sacc + b_out[0];
    }
}

// ---------------------------------------------------------------------------
// Launch
// ---------------------------------------------------------------------------
extern "C" void kernel_launch(void* const* d_in, const int* in_sizes, int n_in,
                              void* d_out, int out_size)
{
    const float* x       = (const float*)d_in[0];
    const float* statics = (const float*)d_in[1];
    const float* mask    = (const float*)d_in[2];
    const float* delta   = (const float*)d_in[3];
    const float* xlast   = (const float*)d_in[4];
    const float* x_mean  = (const float*)d_in[5];
    const float* hs0     = (const float*)d_in[6];
    const float* w_dg_x  = (const float*)d_in[7];
    const float* b_dg_x  = (const float*)d_in[8];
    const float* W_dg_h  = (const float*)d_in[9];
    const float* b_dg_h  = (const float*)d_in[10];
    const float* W_z = (const float*)d_in[11];
    const float* U_z = (const float*)d_in[12];
    const float* V_z = (const float*)d_in[13];
    const float* b_z = (const float*)d_in[14];
    const float* W_r = (const float*)d_in[15];
    const float* U_r = (const float*)d_in[16];
    const float* V_r = (const float*)d_in[17];
    const float* b_r = (const float*)d_in[18];
    const float* W_h = (const float*)d_in[19];
    const float* U_h = (const float*)d_in[20];
    const float* V_h = (const float*)d_in[21];
    const float* b_h = (const float*)d_in[22];
    const float* W_out = (const float*)d_in[23];
    const float* b_out = (const float*)d_in[24];
    float* out = (float*)d_out;

    cudaFuncSetAttribute(precompute_mma, cudaFuncAttributeMaxDynamicSharedMemorySize, SM_TOTAL);
    cudaFuncSetAttribute(recurrent_mma, cudaFuncAttributeMaxDynamicSharedMemorySize, R_TOTAL);

    // one no-op: ncu capture (4th launch slot) lands on recurrent_mma
    noop_kernel<<<1, 32>>>();
    convert_w<<<10, 256>>>(W_z, V_z, W_r, V_r, W_h, V_h, W_dg_h, U_z, U_r, U_h);
    precompute_mma<<<BT / 128, 256, SM_TOTAL>>>(x, mask, delta, xlast, x_mean,
                                                w_dg_x, b_dg_x, b_dg_h, b_z, b_r, b_h);
    recurrent_mma<<<BB / 16, 256, R_TOTAL>>>(hs0, statics, W_out, b_out, out);
}

// round 17
// speedup vs baseline: 1.6646x; 1.6646x over previous
#include <cuda_runtime.h>
#include <cuda_bf16.h>
#include <cstddef>
#include <cstdint>

// Problem constants
#define BB 512
#define TT 256
#define DD 128
#define HH 128
#define SS 32
#define BT (BB*TT)   // 131072

typedef unsigned long long u64;
typedef uint32_t u32;

// ---------------------------------------------------------------------------
// f32x2 packed-math helpers (recurrence)
// ---------------------------------------------------------------------------
__device__ __forceinline__ u64 ffma2(u64 a, u64 b, u64 c) {
    u64 d;
    asm("fma.rn.f32x2 %0, %1, %2, %3;" : "=l"(d) : "l"(a), "l"(b), "l"(c));
    return d;
}
__device__ __forceinline__ u64 add2(u64 a, u64 b) {
    u64 d;
    asm("add.rn.f32x2 %0, %1, %2;" : "=l"(d) : "l"(a), "l"(b));
    return d;
}
__device__ __forceinline__ u64 pack2(float v) {
    u64 d;
    asm("mov.b64 %0, {%1, %1};" : "=l"(d) : "f"(v));
    return d;
}
__device__ __forceinline__ u64 packab(float a, float b) {
    u64 d;
    asm("mov.b64 %0, {%1, %2};" : "=l"(d) : "f"(a), "f"(b));
    return d;
}
__device__ __forceinline__ float2 unpk(u64 x) {
    float2 f;
    asm("mov.b64 {%0, %1}, %2;" : "=f"(f.x), "=f"(f.y) : "l"(x));
    return f;
}
union F4U2 { float4 f; u64 u[2]; };

// ---------------------------------------------------------------------------
// Device-global scratch
// ---------------------------------------------------------------------------
__device__ float g_Xz[(size_t)BT * HH];
__device__ float g_Xr[(size_t)BT * HH];
__device__ float g_Xh[(size_t)BT * HH];
__device__ float g_gh[(size_t)BT * HH];
// bf16 hi/lo copies [j][d]: 0=W_z 1=V_z 2=W_r 3=V_r 4=W_h 5=V_h 6=W_dg_h
__device__ __nv_bfloat16 g_Wbh[7 * 16384];
__device__ __nv_bfloat16 g_Wbl[7 * 16384];

__global__ void noop_kernel() {}

// ---------------------------------------------------------------------------
// Kernel 0: convert 7 weight matrices fp32 -> bf16 hi/lo
// ---------------------------------------------------------------------------
__global__ void convert_w(const float* __restrict__ Wz, const float* __restrict__ Vz,
                          const float* __restrict__ Wr, const float* __restrict__ Vr,
                          const float* __restrict__ Wh, const float* __restrict__ Vh,
                          const float* __restrict__ Wdgh)
{
    const float* srcs[7] = {Wz, Vz, Wr, Vr, Wh, Vh, Wdgh};
    const float* s = srcs[blockIdx.x];
    __nv_bfloat16* dh = g_Wbh + blockIdx.x * 16384;
    __nv_bfloat16* dl = g_Wbl + blockIdx.x * 16384;
    for (int idx = threadIdx.x; idx < 16384; idx += blockDim.x) {
        float v = s[idx];
        __nv_bfloat16 h = __float2bfloat16(v);
        dh[idx] = h;
        dl[idx] = __float2bfloat16(v - __bfloat162float(h));
    }
}

// ---------------------------------------------------------------------------
// Kernel 1: precompute via HMMA. 1024 blocks x 512 threads (16 warps),
// warp tile 16 rows x 64 cols -> 4 warps/SMSP for latency hiding.
// ---------------------------------------------------------------------------
#define PA 136
#define PANEL_B (128 * PA * 2)
#define SM_BIAS  0
#define SM_AHI   512
#define SM_ALO   (SM_AHI + PANEL_B)
#define SM_MBF   (SM_ALO + PANEL_B)
#define SM_WHI   (SM_MBF + PANEL_B)
#define SM_WLO   (SM_WHI + PANEL_B)
#define SM_TOTAL (SM_WLO + PANEL_B)      // 174592

__device__ __forceinline__ void mma_bf16(float c[4], u32 a0, u32 a1, u32 a2, u32 a3,
                                         u32 b0, u32 b1) {
    asm("mma.sync.aligned.m16n8k16.row.col.f32.bf16.bf16.f32 "
        "{%0,%1,%2,%3}, {%4,%5,%6,%7}, {%8,%9}, {%0,%1,%2,%3};"
        : "+f"(c[0]), "+f"(c[1]), "+f"(c[2]), "+f"(c[3])
        : "r"(a0), "r"(a1), "r"(a2), "r"(a3), "r"(b0), "r"(b1));
}
__device__ __forceinline__ void ldsm4(u32& r0, u32& r1, u32& r2, u32& r3, u32 a) {
    asm volatile("ldmatrix.sync.aligned.m8n8.x4.shared.b16 {%0,%1,%2,%3}, [%4];"
                 : "=r"(r0), "=r"(r1), "=r"(r2), "=r"(r3) : "r"(a));
}

// single pass, 16-row tile: acc[8][4] += A(row0..row0+15) @ W^T(col0..col0+63)
__device__ __forceinline__ void gp16(const __nv_bfloat16* __restrict__ A,
                                     const __nv_bfloat16* __restrict__ W,
                                     float acc[8][4], int row0, int col0, int lane)
{
    const int ar = lane & 15, ac = (lane >> 4) << 3;
    const int bj = ((lane >> 4) << 3) + (lane & 7);
    const int bk = ((lane >> 3) & 1) << 3;
    #pragma unroll
    for (int kt = 0; kt < 8; kt++) {
        const int k0 = kt * 16;
        u32 a[4];
        u32 ad = (u32)__cvta_generic_to_shared(A + (row0 + ar) * PA + k0 + ac);
        ldsm4(a[0], a[1], a[2], a[3], ad);
        u32 b[4][4];
        #pragma unroll
        for (int np = 0; np < 4; np++) {
            u32 bd = (u32)__cvta_generic_to_shared(W + (col0 + np * 16 + bj) * PA + k0 + bk);
            ldsm4(b[np][0], b[np][1], b[np][2], b[np][3], bd);
        }
        #pragma unroll
        for (int nt = 0; nt < 8; nt++)
            mma_bf16(acc[nt], a[0], a[1], a[2], a[3],
                     b[nt >> 1][(nt & 1) * 2], b[nt >> 1][(nt & 1) * 2 + 1]);
    }
}

// dual-A: acc += A0 @ W^T + A1 @ W^T (B frags loaded once)
__device__ __forceinline__ void gp16AA(const __nv_bfloat16* __restrict__ A0,
                                       const __nv_bfloat16* __restrict__ A1,
                                       const __nv_bfloat16* __restrict__ W,
                                       float acc[8][4], int row0, int col0, int lane)
{
    const int ar = lane & 15, ac = (lane >> 4) << 3;
    const int bj = ((lane >> 4) << 3) + (lane & 7);
    const int bk = ((lane >> 3) & 1) << 3;
    #pragma unroll
    for (int kt = 0; kt < 8; kt++) {
        const int k0 = kt * 16;
        u32 a0[4], a1[4];
        u32 ad0 = (u32)__cvta_generic_to_shared(A0 + (row0 + ar) * PA + k0 + ac);
        ldsm4(a0[0], a0[1], a0[2], a0[3], ad0);
        u32 ad1 = (u32)__cvta_generic_to_shared(A1 + (row0 + ar) * PA + k0 + ac);
        ldsm4(a1[0], a1[1], a1[2], a1[3], ad1);
        u32 b[4][4];
        #pragma unroll
        for (int np = 0; np < 4; np++) {
            u32 bd = (u32)__cvta_generic_to_shared(W + (col0 + np * 16 + bj) * PA + k0 + bk);
            ldsm4(b[np][0], b[np][1], b[np][2], b[np][3], bd);
        }
        #pragma unroll
        for (int nt = 0; nt < 8; nt++) {
            mma_bf16(acc[nt], a0[0], a0[1], a0[2], a0[3],
                     b[nt >> 1][(nt & 1) * 2], b[nt >> 1][(nt & 1) * 2 + 1]);
            mma_bf16(acc[nt], a1[0], a1[1], a1[2], a1[3],
                     b[nt >> 1][(nt & 1) * 2], b[nt >> 1][(nt & 1) * 2 + 1]);
        }
    }
}

// dual-B: acc += A @ W0^T + A @ W1^T (A frags loaded once)
__device__ __forceinline__ void gp16BB(const __nv_bfloat16* __restrict__ A,
                                       const __nv_bfloat16* __restrict__ W0,
                                       const __nv_bfloat16* __restrict__ W1,
                                       float acc[8][4], int row0, int col0, int lane)
{
    const int ar = lane & 15, ac = (lane >> 4) << 3;
    const int bj = ((lane >> 4) << 3) + (lane & 7);
    const int bk = ((lane >> 3) & 1) << 3;
    #pragma unroll
    for (int kt = 0; kt < 8; kt++) {
        const int k0 = kt * 16;
        u32 a[4];
        u32 ad = (u32)__cvta_generic_to_shared(A + (row0 + ar) * PA + k0 + ac);
        ldsm4(a[0], a[1], a[2], a[3], ad);
        u32 b0[4][4], b1[4][4];
        #pragma unroll
        for (int np = 0; np < 4; np++) {
            u32 bd0 = (u32)__cvta_generic_to_shared(W0 + (col0 + np * 16 + bj) * PA + k0 + bk);
            ldsm4(b0[np][0], b0[np][1], b0[np][2], b0[np][3], bd0);
            u32 bd1 = (u32)__cvta_generic_to_shared(W1 + (col0 + np * 16 + bj) * PA + k0 + bk);
            ldsm4(b1[np][0], b1[np][1], b1[np][2], b1[np][3], bd1);
        }
        #pragma unroll
        for (int nt = 0; nt < 8; nt++) {
            mma_bf16(acc[nt], a[0], a[1], a[2], a[3],
                     b0[nt >> 1][(nt & 1) * 2], b0[nt >> 1][(nt & 1) * 2 + 1]);
            mma_bf16(acc[nt], a[0], a[1], a[2], a[3],
                     b1[nt >> 1][(nt & 1) * 2], b1[nt >> 1][(nt & 1) * 2 + 1]);
        }
    }
}

__device__ __forceinline__ void stage_w(char* smem, int off, const __nv_bfloat16* g) {
    const uint4* src = (const uint4*)g;   // 2048 chunks
    #pragma unroll
    for (int it = 0; it < 4; it++) {
        int cc = threadIdx.x + it * 512;
        int j = cc >> 4, k8 = (cc & 15) * 8;
        *(uint4*)(smem + off + (j * PA + k8) * 2) = src[cc];
    }
}

__global__ __launch_bounds__(512, 1)
void precompute_mma(const float* __restrict__ x,     const float* __restrict__ mask,
                    const float* __restrict__ delta, const float* __restrict__ xlast,
                    const float* __restrict__ x_mean,
                    const float* __restrict__ w_dg_x, const float* __restrict__ b_dg_x,
                    const float* __restrict__ b_dg_h,
                    const float* __restrict__ b_z, const float* __restrict__ b_r,
                    const float* __restrict__ b_h)
{
    extern __shared__ char smem[];
    float* bias_s = (float*)(smem + SM_BIAS);
    __nv_bfloat16* Ahi = (__nv_bfloat16*)(smem + SM_AHI);
    __nv_bfloat16* Alo = (__nv_bfloat16*)(smem + SM_ALO);
    __nv_bfloat16* Mbf = (__nv_bfloat16*)(smem + SM_MBF);
    __nv_bfloat16* Whi = (__nv_bfloat16*)(smem + SM_WHI);
    __nv_bfloat16* Wlo = (__nv_bfloat16*)(smem + SM_WLO);

    const int tid  = threadIdx.x;
    const int lane = tid & 31;
    const int wrp  = tid >> 5;                 // 0..15
    const int row0 = (wrp & 7) * 16;           // 8 row groups
    const int col0 = (wrp >> 3) * 64;          // 2 col groups
    const int brow = blockIdx.x * 128;
    const int b    = brow >> 8;
    const int g = lane >> 2, t = lane & 3;

    float acc[8][4];

    // ---- pass 1 panels: delta hi/lo ----
    for (int idx = tid; idx < 128 * 128; idx += 512) {
        int r = idx >> 7, d = idx & 127;
        float v = delta[(size_t)(brow + r) * DD + d];
        __nv_bfloat16 hi = __float2bfloat16(v);
        Ahi[r * PA + d] = hi;
        Alo[r * PA + d] = __float2bfloat16(v - __bfloat162float(hi));
    }
    stage_w(smem, SM_WHI, g_Wbh + 6 * 16384);
    stage_w(smem, SM_WLO, g_Wbl + 6 * 16384);
    if (tid < 128) bias_s[tid] = b_dg_h[tid];
    __syncthreads();

    // ---- gamma_h ----
    #pragma unroll
    for (int nt = 0; nt < 8; nt++)
        #pragma unroll
        for (int q = 0; q < 4; q++) acc[nt][q] = 0.0f;
    gp16AA(Ahi, Alo, Whi, acc, row0, col0, lane);
    gp16(Ahi, Wlo, acc, row0, col0, lane);
    #pragma unroll
    for (int nt = 0; nt < 8; nt++) {
        int j0 = col0 + nt * 8 + 2 * t;
        float2 bv = *(const float2*)&bias_s[j0];
        size_t r0g = (size_t)(brow + row0 + g) * HH + j0;
        size_t r8g = r0g + (size_t)8 * HH;
        *(float2*)&g_gh[r0g] = make_float2(__expf(-fmaxf(acc[nt][0] + bv.x, 0.0f)),
                                           __expf(-fmaxf(acc[nt][1] + bv.y, 0.0f)));
        *(float2*)&g_gh[r8g] = make_float2(__expf(-fmaxf(acc[nt][2] + bv.x, 0.0f)),
                                           __expf(-fmaxf(acc[nt][3] + bv.y, 0.0f)));
    }
    __syncthreads();

    // ---- pass 2 panels: x_hat hi/lo, mask ----
    for (int idx = tid; idx < 128 * 128; idx += 512) {
        int r = idx >> 7, d = idx & 127;
        size_t gg = (size_t)(brow + r) * DD + d;
        float xv = x[gg], mv = mask[gg], dl = delta[gg], xl = xlast[gg];
        float gx = __expf(-fmaxf(fmaf(w_dg_x[d], dl, b_dg_x[d]), 0.0f));
        float xm = x_mean[b * DD + d];
        float xh = mv * xv + (1.0f - mv) * (gx * xl + (1.0f - gx) * xm);
        __nv_bfloat16 hi = __float2bfloat16(xh);
        Ahi[r * PA + d] = hi;
        Alo[r * PA + d] = __float2bfloat16(xh - __bfloat162float(hi));
        Mbf[r * PA + d] = __float2bfloat16(mv);
    }
    __syncthreads();

    const int wi[3] = {0, 2, 4};
    const int vi[3] = {1, 3, 5};
    const float* biases[3] = {b_z, b_r, b_h};
    float* outs[3] = {g_Xz, g_Xr, g_Xh};

    #pragma unroll 1
    for (int gate = 0; gate < 3; gate++) {
        stage_w(smem, SM_WHI, g_Wbh + wi[gate] * 16384);
        stage_w(smem, SM_WLO, g_Wbl + wi[gate] * 16384);
        if (tid < 128) bias_s[tid] = biases[gate][tid];
        __syncthreads();

        #pragma unroll
        for (int nt = 0; nt < 8; nt++)
            #pragma unroll
            for (int q = 0; q < 4; q++) acc[nt][q] = 0.0f;

        gp16AA(Ahi, Alo, Whi, acc, row0, col0, lane);
        gp16(Ahi, Wlo, acc, row0, col0, lane);

        __syncthreads();
        stage_w(smem, SM_WHI, g_Wbh + vi[gate] * 16384);
        stage_w(smem, SM_WLO, g_Wbl + vi[gate] * 16384);
        __syncthreads();
        gp16BB(Mbf, Whi, Wlo, acc, row0, col0, lane);

        float* obase = outs[gate];
        #pragma unroll
        for (int nt = 0; nt < 8; nt++) {
            int j0 = col0 + nt * 8 + 2 * t;
            float2 bv = *(const float2*)&bias_s[j0];
            size_t r0g = (size_t)(brow + row0 + g) * HH + j0;
            size_t r8g = r0g + (size_t)8 * HH;
            *(float2*)&obase[r0g] = make_float2(acc[nt][0] + bv.x, acc[nt][1] + bv.y);
            *(float2*)&obase[r8g] = make_float2(acc[nt][2] + bv.x, acc[nt][3] + bv.y);
        }
        __syncthreads();
    }
}

// ---------------------------------------------------------------------------
// Kernel 2: recurrence (R11 verbatim — best known: 643 us).
// ---------------------------------------------------------------------------
#define PUS 129
#define OFS_UZ  0
#define OFS_UR  16512
#define OFS_UH2 33024
#define OFS_HT  (OFS_UH2 + 16384)
#define OFS_RHT (OFS_HT + 512)
#define OFS_XZR (OFS_RHT + 512)
#define OFS_XH  (OFS_XZR + 1024)
#define SMEMB_FL (OFS_XH + 512)           // 51968 fl = 207872 B

__global__ __launch_bounds__(256, 1)
void recurrent_kernel(const float* __restrict__ hs0,
                      const float* __restrict__ Uz, const float* __restrict__ Ur,
                      const float* __restrict__ Uh,
                      const float* __restrict__ statics,
                      const float* __restrict__ W_out, const float* __restrict__ b_out,
                      float* __restrict__ out)
{
    extern __shared__ float sm[];
    float*  UzS  = sm + OFS_UZ;
    float*  UrS  = sm + OFS_UR;
    float2* Uh2  = (float2*)(sm + OFS_UH2);
    float*  hT   = sm + OFS_HT;
    float*  rhT  = sm + OFS_RHT;
    u64*    xchZR = (u64*)(sm + OFS_XZR);
    u64*    xchH  = (u64*)(sm + OFS_XH);

    const int tid  = threadIdx.x;
    const int j    = tid & 127;
    const bool h0  = tid < 128;
    const int k0   = h0 ? 0 : 64;
    const int kq0  = h0 ? 0 : 32;
    const int b0   = blockIdx.x * 4;

    for (int idx = tid; idx < HH * HH; idx += 256) {
        int jj = idx >> 7, k = idx & 127;
        UzS[k * PUS + jj] = Uz[idx];
        UrS[k * PUS + jj] = Ur[idx];
    }
    for (int idx = tid; idx < 64 * 128; idx += 256) {
        int kp = idx >> 7, jj = idx & 127;
        Uh2[kp * 128 + jj] = make_float2(Uh[jj * 128 + 2 * kp],
                                         Uh[jj * 128 + 2 * kp + 1]);
    }

    float hreg[4], cG[4], cXz[4], cXr[4], cXh[4], zg[4];
    if (h0) {
        #pragma unroll
        for (int r = 0; r < 4; r++) {
            hreg[r] = hs0[(b0 + r) * HH + j];
            int g = ((b0 + r) * TT) * HH + j;
            cG[r] = g_gh[g]; cXz[r] = g_Xz[g]; cXr[r] = g_Xr[g]; cXh[r] = g_Xh[g];
        }
    }
    __syncthreads();

    float uzr_[64], urr_[64];
    #pragma unroll
    for (int kk = 0; kk < 64; kk++) {
        uzr_[kk] = UzS[(k0 + kk) * PUS + j];
        urr_[kk] = UrS[(k0 + kk) * PUS + j];
    }

    u64 sz01 = 0, sz23 = 0, sr01 = 0, sr23 = 0, sh01 = 0, sh23 = 0;

    #pragma unroll 1
    for (int t = 0; t < TT; t++) {
        if (h0) {
            #pragma unroll
            for (int r = 0; r < 4; r++) hreg[r] *= cG[r];
            *(float4*)&hT[j * 4] = make_float4(hreg[0], hreg[1], hreg[2], hreg[3]);
        }
        __syncthreads();   // B1

        if (h0) {
            sz01 = packab(cXz[0], cXz[1]); sz23 = packab(cXz[2], cXz[3]);
            sr01 = packab(cXr[0], cXr[1]); sr23 = packab(cXr[2], cXr[3]);
            sh01 = packab(cXh[0], cXh[1]); sh23 = packab(cXh[2], cXh[3]);
            if (t + 1 < TT) {
                #pragma unroll
                for (int r = 0; r < 4; r++) {
                    int g = ((b0 + r) * TT + t + 1) * HH + j;
                    cG[r] = g_gh[g]; cXz[r] = g_Xz[g];
                    cXr[r] = g_Xr[g]; cXh[r] = g_Xh[g];
                }
            }
        }

        u64 az01 = 0, az23 = 0, ar01 = 0, ar23 = 0;
        #pragma unroll
        for (int kk = 0; kk < 64; kk++) {
            F4U2 hv; hv.f = *(const float4*)&hT[(k0 + kk) * 4];
            u64 uz2 = pack2(uzr_[kk]);
            u64 ur2 = pack2(urr_[kk]);
            az01 = ffma2(hv.u[0], uz2, az01);
            az23 = ffma2(hv.u[1], uz2, az23);
            ar01 = ffma2(hv.u[0], ur2, ar01);
            ar23 = ffma2(hv.u[1], ur2, ar23);
        }

        if (!h0) {
            xchZR[4 * j]     = az01;
            xchZR[4 * j + 1] = az23;
            xchZR[4 * j + 2] = ar01;
            xchZR[4 * j + 3] = ar23;
        }
        __syncthreads();   // B2

        if (h0) {
            u64 qz01 = xchZR[4 * j],     qz23 = xchZR[4 * j + 1];
            u64 qr01 = xchZR[4 * j + 2], qr23 = xchZR[4 * j + 3];
            float2 z01 = unpk(add2(add2(az01, qz01), sz01));
            float2 z23 = unpk(add2(add2(az23, qz23), sz23));
            float2 r01 = unpk(add2(add2(ar01, qr01), sr01));
            float2 r23 = unpk(add2(add2(ar23, qr23), sr23));
            zg[0] = 1.0f / (1.0f + __expf(-z01.x));
            zg[1] = 1.0f / (1.0f + __expf(-z01.y));
            zg[2] = 1.0f / (1.0f + __expf(-z23.x));
            zg[3] = 1.0f / (1.0f + __expf(-z23.y));
            float rg0 = 1.0f / (1.0f + __expf(-r01.x));
            float rg1 = 1.0f / (1.0f + __expf(-r01.y));
            float rg2 = 1.0f / (1.0f + __expf(-r23.x));
            float rg3 = 1.0f / (1.0f + __expf(-r23.y));
            *(float4*)&rhT[j * 4] = make_float4(rg0 * hreg[0], rg1 * hreg[1],
                                                rg2 * hreg[2], rg3 * hreg[3]);
        }
        __syncthreads();   // B3

        u64 ah01 = h0 ? sh01 : 0ull;
        u64 ah23 = h0 ? sh23 : 0ull;
        #pragma unroll 8
        for (int kp = kq0; kp < kq0 + 32; kp++) {
            int k4 = kp * 8;
            F4U2 re; re.f = *(const float4*)&rhT[k4];
            F4U2 ro; ro.f = *(const float4*)&rhT[k4 + 4];
            float2 u2 = Uh2[kp * 128 + j];
            u64 uhe = pack2(u2.x), uho = pack2(u2.y);
            ah01 = ffma2(re.u[0], uhe, ah01);
            ah23 = ffma2(re.u[1], uhe, ah23);
            ah01 = ffma2(ro.u[0], uho, ah01);
            ah23 = ffma2(ro.u[1], uho, ah23);
        }
        if (!h0) {
            xchH[2 * j]     = ah01;
            xchH[2 * j + 1] = ah23;
        }
        __syncthreads();   // B4

        if (h0) {
            float2 p01 = unpk(add2(ah01, xchH[2 * j]));
            float2 p23 = unpk(add2(ah23, xchH[2 * j + 1]));
            float pre[4] = {p01.x, p01.y, p23.x, p23.y};
            #pragma unroll
            for (int r = 0; r < 4; r++) {
                float ht = 2.0f / (1.0f + __expf(-2.0f * pre[r])) - 1.0f;
                hreg[r] = (1.0f - zg[r]) * hreg[r] + zg[r] * ht;
            }
        }
    }

    // ---- classifier ----
    __syncthreads();
    if (h0) {
        float wj = W_out[j];
        *(float4*)&hT[j * 4] = make_float4(hreg[0] * wj, hreg[1] * wj,
                                           hreg[2] * wj, hreg[3] * wj);
    }
    __syncthreads();
    for (int s = 64; s > 0; s >>= 1) {
        if (tid < s) {
            float4 a = *(const float4*)&hT[tid * 4];
            float4 c = *(const float4*)&hT[(tid + s) * 4];
            a.x += c.x; a.y += c.y; a.z += c.z; a.w += c.w;
            *(float4*)&hT[tid * 4] = a;
        }
        __syncthreads();
    }
    if (tid < 4) {
        float v = hT[tid];
        float sacc = 0.0f;
        #pragma unroll
        for (int s = 0; s < SS; s++)
            sacc = fmaf(statics[(b0 + tid) * SS + s], W_out[HH + s], sacc);
        out[b0 + tid] = v + sacc + b_out[0];
    }
}

// ---------------------------------------------------------------------------
// Launch
// ---------------------------------------------------------------------------
extern "C" void kernel_launch(void* const* d_in, const int* in_sizes, int n_in,
                              void* d_out, int out_size)
{
    const float* x       = (const float*)d_in[0];
    const float* statics = (const float*)d_in[1];
    const float* mask    = (const float*)d_in[2];
    const float* delta   = (const float*)d_in[3];
    const float* xlast   = (const float*)d_in[4];
    const float* x_mean  = (const float*)d_in[5];
    const float* hs0     = (const float*)d_in[6];
    const float* w_dg_x  = (const float*)d_in[7];
    const float* b_dg_x  = (const float*)d_in[8];
    const float* W_dg_h  = (const float*)d_in[9];
    const float* b_dg_h  = (const float*)d_in[10];
    const float* W_z = (const float*)d_in[11];
    const float* U_z = (const float*)d_in[12];
    const float* V_z = (const float*)d_in[13];
    const float* b_z = (const float*)d_in[14];
    const float* W_r = (const float*)d_in[15];
    const float* U_r = (const float*)d_in[16];
    const float* V_r = (const float*)d_in[17];
    const float* b_r = (const float*)d_in[18];
    const float* W_h = (const float*)d_in[19];
    const float* U_h = (const float*)d_in[20];
    const float* V_h = (const float*)d_in[21];
    const float* b_h = (const float*)d_in[22];
    const float* W_out = (const float*)d_in[23];
    const float* b_out = (const float*)d_in[24];
    float* out = (float*)d_out;

    const int smemB = SMEMB_FL * (int)sizeof(float);   // 207872
    cudaFuncSetAttribute(precompute_mma, cudaFuncAttributeMaxDynamicSharedMemorySize, SM_TOTAL);
    cudaFuncSetAttribute(recurrent_kernel, cudaFuncAttributeMaxDynamicSharedMemorySize, smemB);

    // two no-ops: ncu capture lands on precompute_mma (slot 4)
    noop_kernel<<<1, 32>>>();
    noop_kernel<<<1, 32>>>();
    convert_w<<<7, 256>>>(W_z, V_z, W_r, V_r, W_h, V_h, W_dg_h);
    precompute_mma<<<BT / 128, 512, SM_TOTAL>>>(x, mask, delta, xlast, x_mean,
                                                w_dg_x, b_dg_x, b_dg_h, b_z, b_r, b_h);
    recurrent_kernel<<<BB / 4, 256, smemB>>>(hs0, U_z, U_r, U_h,
                                             statics, W_out, b_out, out);
}